// round 13
// baseline (speedup 1.0000x reference)
#include <cuda_runtime.h>
#include <cuda_fp16.h>
#include <stdint.h>
#include <math.h>

#define BB     64
#define NCH    129
#define NT     200
#define DM     256
#define DSTATE 16
#define HD     32
#define NL     4
#define DI     512
#define NH     16
#define CONVD  544
#define DPROJ  1072
#define TOK    (BB*NT)   // 12800
#define KPAD   160       // 129 padded to mult of 32 (K32 gemm stages)
#define SMH    40        // smem row stride in halfs (32+8) -> ldmatrix conflict-free
#define TTILE  20
#define TSEG   25

#define NW_IN  (NL*DPROJ*DM)
#define NW_OUT (NL*DM*DI)
#define STAGEB (128*SMH*2)            // 10240 B per matrix per stage
#define GSMEM  (3*2*STAGEB)           // 61440 B: 3 stages x (A,B)

// ---------------- scratch ---------------------------------------------------
__device__ __align__(16) __half g_xsr[TOK*KPAD];
__device__ __align__(16) __half g_mixw[DM*KPAD];
__device__ float  g_biasenc[DM];
__device__ __align__(16) __half g_h[TOK*DM];
__device__ float  g_zx[TOK*DPROJ];
__device__ float  g_bc[TOK*64];       // [B16, C16, dA16, dt16] per token
__device__ __align__(16) __half g_y[TOK*DI];
__device__ float  g_o[TOK*DM];
__device__ float  g_ss[2*TOK];
__device__ __align__(16) __half g_wrnd[NW_IN + NW_OUT];

// ---------------- helpers ---------------------------------------------------
__device__ __forceinline__ float siluf(float x) { return x / (1.f + expf(-x)); }

__device__ __forceinline__ void mma_f16(float* c, const uint32_t* a, const uint32_t* b) {
    asm volatile("mma.sync.aligned.m16n8k16.row.col.f32.f16.f16.f32 "
        "{%0,%1,%2,%3}, {%4,%5,%6,%7}, {%8,%9}, {%0,%1,%2,%3};"
        : "+f"(c[0]), "+f"(c[1]), "+f"(c[2]), "+f"(c[3])
        : "r"(a[0]), "r"(a[1]), "r"(a[2]), "r"(a[3]), "r"(b[0]), "r"(b[1]));
}
__device__ __forceinline__ void cpa16(uint32_t dst, const void* src, int sz) {
    asm volatile("cp.async.ca.shared.global [%0], [%1], 16, %2;"
                 :: "r"(dst), "l"(src), "r"(sz));
}
__device__ __forceinline__ void ldm_x4(uint32_t addr, uint32_t* r) {
    asm volatile("ldmatrix.sync.aligned.m8n8.x4.shared.b16 {%0,%1,%2,%3}, [%4];"
        : "=r"(r[0]), "=r"(r[1]), "=r"(r[2]), "=r"(r[3]) : "r"(addr));
}

// ---------------- FP16 GEMM, 3-stage K32, ldmatrix, fp32 accum --------------
// K % 32 == 0. If ssbuf != null: row scale rsqrt((ss0+ss1)/512 + 1e-5).
__global__ void __launch_bounds__(256, 2)
gemm_f16(const __half* __restrict__ A, const __half* __restrict__ W,
         const float* __restrict__ bias, const float* __restrict__ ssbuf,
         float* __restrict__ C, int M, int N, int K) {
    extern __shared__ __half dsm[];
    const int bm = blockIdx.y * 128, bn = blockIdx.x * 128;
    const int tid = threadIdx.x, lane = tid & 31, warp = tid >> 5;
    const int wm = (warp & 1) * 64, wn = (warp >> 1) * 32;
    const int r0 = lane >> 2, c0 = lane & 3;

    float acc[4][4][4];
#pragma unroll
    for (int i = 0; i < 4; i++)
#pragma unroll
        for (int j = 0; j < 4; j++)
#pragma unroll
            for (int k = 0; k < 4; k++) acc[i][j][k] = 0.f;

    // loader: row = tid>>1; two 16B chunks per row per stage (K=32 halfs)
    const int lrow = tid >> 1, lch = (tid & 1) * 8;
    const __half* Ap = A + (size_t)(bm + lrow) * K + lch;
    const int bnr = bn + lrow;
    const __half* Bp = W + (size_t)(bnr < N ? bnr : 0) * K + lch;
    const int szb = bnr < N ? 16 : 0;

    const uint32_t base = (uint32_t)__cvta_generic_to_shared(dsm);
    const uint32_t dof = (uint32_t)(lrow * SMH + lch) * 2u;

    const int lane7 = lane & 7;
    const int arow8 = ((lane >> 3) & 1) * 8, acol8 = ((lane >> 4) & 1) * 8;
    const int brow8 = ((lane >> 4) & 1) * 8, bcol8 = ((lane >> 3) & 1) * 8;
    uint32_t aAf[4], aBf[2];
#pragma unroll
    for (int mi = 0; mi < 4; mi++)
        aAf[mi] = base + (uint32_t)(((wm + mi * 16 + lane7 + arow8) * SMH + acol8) * 2);
#pragma unroll
    for (int njp = 0; njp < 2; njp++)
        aBf[njp] = base + 3u * STAGEB +
                   (uint32_t)(((wn + njp * 16 + lane7 + brow8) * SMH + bcol8) * 2);

    const int KT = K >> 5;   // K32 tiles

#define LOADT(kt, buf)                                                   \
    do {                                                                 \
        int ko = (kt) * 32;                                              \
        uint32_t aA = base + (uint32_t)(buf) * STAGEB;                   \
        uint32_t aB = base + (uint32_t)(3 + (buf)) * STAGEB;             \
        cpa16(aA + dof, Ap + ko, 16);                                    \
        cpa16(aA + dof + 32u, Ap + ko + 16, 16);                         \
        cpa16(aB + dof, Bp + ko, szb);                                   \
        cpa16(aB + dof + 32u, Bp + ko + 16, szb);                        \
        asm volatile("cp.async.commit_group;");                          \
    } while (0)

    LOADT(0, 0);
    if (KT > 1) LOADT(1, 1);
    int ib = 2, cb = 0;
    for (int kt = 0; kt < KT; kt++) {
        if (kt < KT - 2) asm volatile("cp.async.wait_group 1;");
        else             asm volatile("cp.async.wait_group 0;");
        __syncthreads();
        if (kt + 2 < KT) {
            LOADT(kt + 2, ib);
            ib = (ib == 2) ? 0 : ib + 1;
        }
        const uint32_t cboff = (uint32_t)cb * STAGEB;
#pragma unroll
        for (int ks = 0; ks < 2; ks++) {
            uint32_t af[4][4], bf[2][4];
#pragma unroll
            for (int mi = 0; mi < 4; mi++) ldm_x4(aAf[mi] + cboff + ks * 32u, af[mi]);
#pragma unroll
            for (int njp = 0; njp < 2; njp++) ldm_x4(aBf[njp] + cboff + ks * 32u, bf[njp]);
#pragma unroll
            for (int mi = 0; mi < 4; mi++)
#pragma unroll
                for (int nj = 0; nj < 4; nj++)
                    mma_f16(acc[mi][nj], af[mi], &bf[nj >> 1][(nj & 1) * 2]);
        }
        cb = (cb == 2) ? 0 : cb + 1;
    }
#undef LOADT

#pragma unroll
    for (int mi = 0; mi < 4; mi++) {
        int row = bm + wm + mi * 16 + r0;
        float sc0 = 1.f, sc1 = 1.f;
        if (ssbuf != nullptr) {
            sc0 = rsqrtf((ssbuf[row] + ssbuf[M + row]) * (1.f / DI) + 1e-5f);
            sc1 = rsqrtf((ssbuf[row + 8] + ssbuf[M + row + 8]) * (1.f / DI) + 1e-5f);
        }
#pragma unroll
        for (int nj = 0; nj < 4; nj++) {
            int col = bn + wn + nj * 8 + c0 * 2;
            if (col < N) {
                float b0 = 0.f, b1 = 0.f;
                if (bias != nullptr) { b0 = bias[col]; b1 = bias[col + 1]; }
                float2 v0 = make_float2(acc[mi][nj][0] * sc0 + b0, acc[mi][nj][1] * sc0 + b1);
                float2 v1 = make_float2(acc[mi][nj][2] * sc1 + b0, acc[mi][nj][3] * sc1 + b1);
                *(float2*)&C[(size_t)row * N + col] = v0;
                *(float2*)&C[(size_t)(row + 8) * N + col] = v1;
            }
        }
    }
}

// ---------------- weight prep: half-round; fold norm_w into out_proj --------
__global__ void k_prepw(const float* __restrict__ wi, const float* __restrict__ wo,
                        const float* __restrict__ nwp) {
    int idx = blockIdx.x * blockDim.x + threadIdx.x;
    if (idx < NW_IN) {
        g_wrnd[idx] = __float2half_rn(wi[idx]);
    } else if (idx < NW_IN + NW_OUT) {
        int j = idx - NW_IN;
        int l = j / (DM * DI);
        int k = j % DI;
        g_wrnd[idx] = __float2half_rn(wo[j] * nwp[l * DI + k]);
    }
}

// ---------------- encoder ---------------------------------------------------
__global__ void k_sconv(const float* __restrict__ x, const float* __restrict__ w,
                        const float* __restrict__ bias) {
    int c = blockIdx.x, b = blockIdx.y, t = threadIdx.x;
    float v = 0.f;
    if (c < NCH) {
        const float* xr = x + (size_t)(b * NCH + c) * NT;
        float w0 = w[c * 3], w1 = w[c * 3 + 1], w2 = w[c * 3 + 2];
        float xm = (t > 0) ? xr[t - 1] : 0.f;
        float x0 = xr[t];
        float xp = (t < NT - 1) ? xr[t + 1] : 0.f;
        v = xm * w0 + x0 * w1 + xp * w2 + bias[c];
    }
    g_xsr[(size_t)(b * NT + t) * KPAD + c] = __float2half_rn(v);
}

// mixprep + biasenc fold
__global__ void k_mixprep(const float* __restrict__ mw,
                          const float* __restrict__ emb, const float* __restrict__ mb) {
    __shared__ float sb[4][64];
    int idx = blockIdx.x * blockDim.x + threadIdx.x;
    if (idx < DM * KPAD) {
        int d = idx / KPAD, k = idx % KPAD;
        g_mixw[idx] = __float2half_rn((k < NCH) ? mw[d * NCH + k] : 0.f);
    }
    if (blockIdx.x < 4) {
        int d = (blockIdx.x << 6) + (threadIdx.x & 63);
        int cg = threadIdx.x >> 6;
        float s = 0.f;
        for (int c = cg; c < NCH; c += 4) s += emb[c * DM + d];
        sb[cg][threadIdx.x & 63] = s;
        __syncthreads();
        if (threadIdx.x < 64) {
            int dd = (blockIdx.x << 6) + threadIdx.x;
            g_biasenc[dd] = mb[dd] +
                (sb[0][threadIdx.x] + sb[1][threadIdx.x] +
                 sb[2][threadIdx.x] + sb[3][threadIdx.x]) * (1.f / NCH);
        }
    }
}

// ---------------- warp-per-row layernorm -------------------------------------
union Pk8 { uint4 u; __half h[8]; };

__global__ void k_ln(const float* __restrict__ in, const __half* __restrict__ res,
                     const float* __restrict__ w, const float* __restrict__ b,
                     __half* __restrict__ out) {
    int row = (blockIdx.x * 256 + threadIdx.x) >> 5;
    int lane = threadIdx.x & 31;
    const float4* ip = (const float4*)(in + (size_t)row * DM + lane * 8);
    float4 a0 = ip[0], a1 = ip[1];
    float v[8] = {a0.x, a0.y, a0.z, a0.w, a1.x, a1.y, a1.z, a1.w};
    if (res != nullptr) {
        Pk8 r;
        r.u = *(const uint4*)(res + (size_t)row * DM + lane * 8);
#pragma unroll
        for (int i = 0; i < 8; i++) v[i] += __half2float(r.h[i]);
    }
    float s = 0.f, s2 = 0.f;
#pragma unroll
    for (int i = 0; i < 8; i++) { s += v[i]; s2 = fmaf(v[i], v[i], s2); }
#pragma unroll
    for (int o = 16; o > 0; o >>= 1) {
        s  += __shfl_xor_sync(0xffffffffu, s,  o);
        s2 += __shfl_xor_sync(0xffffffffu, s2, o);
    }
    float mean = s * (1.f / DM);
    float var  = s2 * (1.f / DM) - mean * mean;
    float inv  = rsqrtf(var + 1e-5f);
    const float4* wp = (const float4*)(w + lane * 8);
    const float4* bp = (const float4*)(b + lane * 8);
    float4 w0 = wp[0], w1 = wp[1], b0 = bp[0], b1 = bp[1];
    float wv[8] = {w0.x, w0.y, w0.z, w0.w, w1.x, w1.y, w1.z, w1.w};
    float bv[8] = {b0.x, b0.y, b0.z, b0.w, b1.x, b1.y, b1.z, b1.w};
    Pk8 o8;
#pragma unroll
    for (int i = 0; i < 8; i++)
        o8.h[i] = __float2half_rn((v[i] - mean) * inv * wv[i] + bv[i]);
    *(uint4*)(out + (size_t)row * DM + lane * 8) = o8.u;
}

// -------- B/C conv+silu and dt/dA precompute into g_bc -----------------------
__global__ void k_bc(const float* __restrict__ cw, const float* __restrict__ cb,
                     const float* __restrict__ dtb, const float* __restrict__ alog) {
    const int b = blockIdx.x;
    const int t0 = blockIdx.y * TSEG;
    const int tid = threadIdx.x;
    const float* zb = g_zx + (size_t)(b * NT) * DPROJ;
    for (int i = tid; i < TSEG * 64; i += 256) {
        const int tl = i >> 6, j = i & 63;
        const int t = t0 + tl;
        const int bt = b * NT + t;
        float outv;
        if (j < 32) {
            const int cc = 512 + j;
            float acc = cb[cc];
            const float* wr = cw + cc * 4;
#pragma unroll
            for (int q = 0; q < 4; q++) {
                int tt = t - 3 + q;
                if (tt >= 0) acc = fmaf(zb[(size_t)tt * DPROJ + DI + cc], wr[q], acc);
            }
            outv = siluf(acc);
        } else {
            const int hh = j & 15;
            float raw = zb[(size_t)t * DPROJ + DI + CONVD + hh] + dtb[hh];
            float d = raw > 20.f ? raw : log1pf(expf(raw));
            outv = (j < 48) ? expf(-d * expf(alog[hh])) : d;
        }
        g_bc[(size_t)bt * 64 + j] = outv;
    }
}

// ---------------- megascan: x-conv+silu+scan+gate+ssq ------------------------
__global__ void k_scan4(const float* __restrict__ cw, const float* __restrict__ cb,
                        const float* __restrict__ Dsk) {
    const int b = blockIdx.x, half = blockIdx.y;
    const int tid = threadIdx.x;                 // 256
    const int h = tid >> 4, p = (tid & 15) + half * 16;
    const int c = h * HD + p;
    const int warp = tid >> 5, lane = tid & 31;
    __shared__ float sB[TTILE][16], sC[TTILE][16];
    __shared__ float sA[TTILE][16], sT[TTILE][16];
    __shared__ float wss[8][NT];

    const float xw0 = cw[c * 4], xw1 = cw[c * 4 + 1];
    const float xw2 = cw[c * 4 + 2], xw3 = cw[c * 4 + 3];
    const float xb = cb[c];
    const float Dh = Dsk[h];
    const int base = b * NT;
    const float* zb = g_zx + (size_t)base * DPROJ;
    const float* bcb = g_bc + (size_t)base * 64;

    float st[DSTATE];
#pragma unroll
    for (int n = 0; n < DSTATE; n++) st[n] = 0.f;
    float hx0 = 0.f, hx1 = 0.f, hx2 = 0.f;

    for (int t0 = 0; t0 < NT; t0 += TTILE) {
        float zg[TTILE], zc[TTILE];
#pragma unroll
        for (int tl = 0; tl < TTILE; tl++) {
            zg[tl] = __ldg(zb + (size_t)(t0 + tl) * DPROJ + c);
            zc[tl] = __ldg(zb + (size_t)(t0 + tl) * DPROJ + DI + c);
        }

        __syncthreads();
#pragma unroll
        for (int i = tid; i < TTILE * 64; i += 256) {
            const int tl = i >> 6, j = i & 63;
            const float v = __ldg(bcb + (size_t)(t0 + tl) * 64 + j);
            if (j < 16)      sB[tl][j] = v;
            else if (j < 32) sC[tl][j - 16] = v;
            else if (j < 48) sA[tl][j - 32] = v;
            else             sT[tl][j - 48] = v;
        }
        __syncthreads();

#pragma unroll
        for (int tl = 0; tl < TTILE; tl++) {
            const float v3 = zc[tl];
            const float xp = siluf(xb + xw0 * hx0 + xw1 * hx1 + xw2 * hx2 + xw3 * v3);
            hx0 = hx1; hx1 = hx2; hx2 = v3;

            const float dAh = sA[tl][h];
            const float dtx = sT[tl][h] * xp;
            float a0 = 0.f, a1 = 0.f;
#pragma unroll
            for (int n = 0; n < DSTATE; n += 2) {
                st[n]     = fmaf(dAh, st[n],     dtx * sB[tl][n]);
                st[n + 1] = fmaf(dAh, st[n + 1], dtx * sB[tl][n + 1]);
                a0 = fmaf(st[n],     sC[tl][n],     a0);
                a1 = fmaf(st[n + 1], sC[tl][n + 1], a1);
            }
            const __half hv = __float2half_rn((a0 + a1 + xp * Dh) * siluf(zg[tl]));
            g_y[(size_t)(base + t0 + tl) * DI + c] = hv;

            const float ov = __half2float(hv);
            float o2 = ov * ov;
#pragma unroll
            for (int o = 16; o > 0; o >>= 1) o2 += __shfl_xor_sync(0xffffffffu, o2, o);
            if (lane == 0) wss[warp][t0 + tl] = o2;
        }
    }

    __syncthreads();
    for (int t = tid; t < NT; t += 256) {
        float s = 0.f;
#pragma unroll
        for (int w = 0; w < 8; w++) s += wss[w][t];
        g_ss[half * TOK + base + t] = s;
    }
}

// ---------------- fused pool + head ------------------------------------------
__global__ void k_poolhead(const float* __restrict__ w1, const float* __restrict__ b1,
                           const float* __restrict__ w2, const float* __restrict__ b2,
                           float* __restrict__ out) {
    __shared__ float sp[DM];
    __shared__ float sh[4];
    int b = blockIdx.x, tid = threadIdx.x;    // 256
    float s = 0.f;
    for (int t = 0; t < NT; t++) s += __half2float(g_h[(size_t)(b * NT + t) * DM + tid]);
    sp[tid] = s * (1.f / NT);
    __syncthreads();
    if (tid < 128) {
        float acc = b1[tid];
        const float* wr = w1 + tid * DM;
#pragma unroll 8
        for (int k = 0; k < DM; k++) acc = fmaf(sp[k], wr[k], acc);
        float r = fmaxf(acc, 0.f) * w2[tid];
#pragma unroll
        for (int o = 16; o > 0; o >>= 1) r += __shfl_xor_sync(0xffffffffu, r, o);
        int lane = tid & 31, wid = tid >> 5;
        if (lane == 0) sh[wid] = r;
    }
    __syncthreads();
    if (tid == 0) out[b] = sh[0] + sh[1] + sh[2] + sh[3] + b2[0];
}

// ---------------- launch -----------------------------------------------------
extern "C" void kernel_launch(void* const* d_in, const int* in_sizes, int n_in,
                              void* d_out, int out_size) {
    const float* x         = (const float*)d_in[0];
    const float* emb       = (const float*)d_in[1];
    const float* sconv_w   = (const float*)d_in[2];
    const float* sconv_b   = (const float*)d_in[3];
    const float* mixer_w   = (const float*)d_in[4];
    const float* mixer_b   = (const float*)d_in[5];
    const float* enc_ln_w  = (const float*)d_in[6];
    const float* enc_ln_b  = (const float*)d_in[7];
    const float* in_proj_w = (const float*)d_in[8];
    const float* conv_w    = (const float*)d_in[9];
    const float* conv_b    = (const float*)d_in[10];
    const float* dt_bias   = (const float*)d_in[11];
    const float* A_log     = (const float*)d_in[12];
    const float* D_skip    = (const float*)d_in[13];
    const float* norm_w    = (const float*)d_in[14];
    const float* out_proj_w= (const float*)d_in[15];
    const float* ln_w      = (const float*)d_in[16];
    const float* ln_b      = (const float*)d_in[17];
    const float* h1w       = (const float*)d_in[18];
    const float* h1b       = (const float*)d_in[19];
    const float* h2w       = (const float*)d_in[20];
    const float* h2b       = (const float*)d_in[21];
    float* out = (float*)d_out;

    __half *xsr, *mixw, *h, *y, *wrnd;
    float *biasenc, *zx, *o, *ss;
    cudaGetSymbolAddress((void**)&xsr,     g_xsr);
    cudaGetSymbolAddress((void**)&mixw,    g_mixw);
    cudaGetSymbolAddress((void**)&biasenc, g_biasenc);
    cudaGetSymbolAddress((void**)&h,       g_h);
    cudaGetSymbolAddress((void**)&zx,      g_zx);
    cudaGetSymbolAddress((void**)&y,       g_y);
    cudaGetSymbolAddress((void**)&o,       g_o);
    cudaGetSymbolAddress((void**)&wrnd,    g_wrnd);
    cudaGetSymbolAddress((void**)&ss,      g_ss);

    cudaFuncSetAttribute(gemm_f16, cudaFuncAttributeMaxDynamicSharedMemorySize, GSMEM);

    // prep
    k_prepw<<<(NW_IN + NW_OUT + 255) / 256, 256>>>(in_proj_w, out_proj_w, norm_w);
    k_sconv<<<dim3(KPAD, BB), NT>>>(x, sconv_w, sconv_b);
    k_mixprep<<<(DM * KPAD + 255) / 256, 256>>>(mixer_w, emb, mixer_b);

    // encoder
    gemm_f16<<<dim3(2, TOK / 128), 256, GSMEM>>>(xsr, mixw, biasenc, nullptr,
                                                 o, TOK, DM, KPAD);
    k_ln<<<TOK / 8, 256>>>(o, nullptr, enc_ln_w, enc_ln_b, h);

    // mamba2 layers
    for (int l = 0; l < NL; l++) {
        gemm_f16<<<dim3((DPROJ + 127) / 128, TOK / 128), 256, GSMEM>>>(
            h, wrnd + (size_t)l * DPROJ * DM, nullptr, nullptr, zx, TOK, DPROJ, DM);
        k_bc<<<dim3(BB, NT / TSEG), 256>>>(conv_w + (size_t)l * CONVD * 4,
                                           conv_b + (size_t)l * CONVD,
                                           dt_bias + l * NH, A_log + l * NH);
        k_scan4<<<dim3(BB, 2), 256>>>(conv_w + (size_t)l * CONVD * 4,
                                      conv_b + (size_t)l * CONVD,
                                      D_skip + l * NH);
        gemm_f16<<<dim3(2, TOK / 128), 256, GSMEM>>>(
            y, wrnd + NW_IN + (size_t)l * DM * DI, nullptr, ss, o, TOK, DM, DI);
        k_ln<<<TOK / 8, 256>>>(o, h, ln_w + l * DM, ln_b + l * DM, h);
    }

    // head
    k_poolhead<<<BB, 256>>>(h1w, h1b, h2w, h2b, out);
}

// round 14
// speedup vs baseline: 1.0292x; 1.0292x over previous
#include <cuda_runtime.h>
#include <cuda_fp16.h>
#include <stdint.h>
#include <math.h>

#define BB     64
#define NCH    129
#define NT     200
#define DM     256
#define DSTATE 16
#define HD     32
#define NL     4
#define DI     512
#define NH     16
#define CONVD  544
#define DPROJ  1072
#define TOK    (BB*NT)   // 12800
#define KPAD   144
#define SMH    24        // smem row stride in halfs -> ldmatrix conflict-free
#define TTILE  20
#define TSEG   25

#define NW_IN  (NL*DPROJ*DM)
#define NW_OUT (NL*DM*DI)
#define STAGEB (128*SMH*2)            // 6144 B per matrix per stage (gemm_f16)
#define GSMEM  (4*2*STAGEB)           // 49152 B
#define GSMEM_LN (4*(64+256)*SMH*2)   // 61440 B (gemm_ln: A 64 rows, B 256 rows)

// ---------------- scratch ---------------------------------------------------
__device__ __align__(16) __half g_xsr[TOK*KPAD];
__device__ __align__(16) __half g_mixw[DM*KPAD];
__device__ float  g_biasenc[DM];
__device__ __align__(16) __half g_h[TOK*DM];
__device__ float  g_zx[TOK*DPROJ];
__device__ float  g_bc[TOK*64];       // [B16, C16, dA16, dt16] per token
__device__ __align__(16) __half g_y[TOK*DI];
__device__ float  g_ss[2*TOK];
__device__ __align__(16) __half g_wrnd[NW_IN + NW_OUT];

// ---------------- helpers ---------------------------------------------------
__device__ __forceinline__ float siluf(float x) { return x / (1.f + expf(-x)); }

__device__ __forceinline__ void mma_f16(float* c, const uint32_t* a, const uint32_t* b) {
    asm volatile("mma.sync.aligned.m16n8k16.row.col.f32.f16.f16.f32 "
        "{%0,%1,%2,%3}, {%4,%5,%6,%7}, {%8,%9}, {%0,%1,%2,%3};"
        : "+f"(c[0]), "+f"(c[1]), "+f"(c[2]), "+f"(c[3])
        : "r"(a[0]), "r"(a[1]), "r"(a[2]), "r"(a[3]), "r"(b[0]), "r"(b[1]));
}
__device__ __forceinline__ void cpa16(uint32_t dst, const void* src, int sz) {
    asm volatile("cp.async.ca.shared.global [%0], [%1], 16, %2;"
                 :: "r"(dst), "l"(src), "r"(sz));
}
__device__ __forceinline__ void ldm_x4(uint32_t addr, uint32_t* r) {
    asm volatile("ldmatrix.sync.aligned.m8n8.x4.shared.b16 {%0,%1,%2,%3}, [%4];"
        : "=r"(r[0]), "=r"(r[1]), "=r"(r[2]), "=r"(r[3]) : "r"(addr));
}

// ---------------- FP16 GEMM (R12 config): 4-stage K16, ldmatrix -------------
__global__ void __launch_bounds__(256, 2)
gemm_f16(const __half* __restrict__ A, const __half* __restrict__ W,
         float* __restrict__ C, int M, int N, int K) {
    extern __shared__ __half dsm[];
    const int bm = blockIdx.y * 128, bn = blockIdx.x * 128;
    const int tid = threadIdx.x, lane = tid & 31, warp = tid >> 5;
    const int wm = (warp & 1) * 64, wn = (warp >> 1) * 32;
    const int r0 = lane >> 2, c0 = lane & 3;

    float acc[4][4][4];
#pragma unroll
    for (int i = 0; i < 4; i++)
#pragma unroll
        for (int j = 0; j < 4; j++)
#pragma unroll
            for (int k = 0; k < 4; k++) acc[i][j][k] = 0.f;

    const int lrow = tid >> 1, lch = (tid & 1) * 8;
    const __half* Ap = A + (size_t)(bm + lrow) * K + lch;
    const int bnr = bn + lrow;
    const __half* Bp = W + (size_t)(bnr < N ? bnr : 0) * K + lch;
    const int szb = bnr < N ? 16 : 0;

    const uint32_t base = (uint32_t)__cvta_generic_to_shared(dsm);
    const uint32_t dof = (uint32_t)(lrow * SMH + lch) * 2u;

    const int lane7 = lane & 7;
    const int arow8 = ((lane >> 3) & 1) * 8, acol8 = ((lane >> 4) & 1) * 8;
    const int brow8 = ((lane >> 4) & 1) * 8, bcol8 = ((lane >> 3) & 1) * 8;
    uint32_t aAf[4], aBf[2];
#pragma unroll
    for (int mi = 0; mi < 4; mi++)
        aAf[mi] = base + (uint32_t)(((wm + mi * 16 + lane7 + arow8) * SMH + acol8) * 2);
#pragma unroll
    for (int njp = 0; njp < 2; njp++)
        aBf[njp] = base + 4u * STAGEB +
                   (uint32_t)(((wn + njp * 16 + lane7 + brow8) * SMH + bcol8) * 2);

    const int KT = K >> 4;

#define LOADT(kt, buf)                                                   \
    do {                                                                 \
        int ko = (kt) * 16;                                              \
        uint32_t aA = base + (uint32_t)(buf) * STAGEB;                   \
        uint32_t aB = base + (uint32_t)(4 + (buf)) * STAGEB;             \
        cpa16(aA + dof, Ap + ko, 16);                                    \
        cpa16(aB + dof, Bp + ko, szb);                                   \
        asm volatile("cp.async.commit_group;");                          \
    } while (0)

    LOADT(0, 0);
    if (KT > 1) LOADT(1, 1);
    if (KT > 2) LOADT(2, 2);
    for (int kt = 0; kt < KT; kt++) {
        if (kt < KT - 3) asm volatile("cp.async.wait_group 2;");
        else             asm volatile("cp.async.wait_group 0;");
        __syncthreads();
        if (kt + 3 < KT) LOADT(kt + 3, (kt + 3) & 3);
        const uint32_t cboff = (uint32_t)(kt & 3) * STAGEB;

        uint32_t af[4][4], bf[2][4];
#pragma unroll
        for (int mi = 0; mi < 4; mi++) ldm_x4(aAf[mi] + cboff, af[mi]);
#pragma unroll
        for (int njp = 0; njp < 2; njp++) ldm_x4(aBf[njp] + cboff, bf[njp]);
#pragma unroll
        for (int mi = 0; mi < 4; mi++)
#pragma unroll
            for (int nj = 0; nj < 4; nj++)
                mma_f16(acc[mi][nj], af[mi], &bf[nj >> 1][(nj & 1) * 2]);
    }
#undef LOADT

#pragma unroll
    for (int mi = 0; mi < 4; mi++) {
        int row = bm + wm + mi * 16 + r0;
#pragma unroll
        for (int nj = 0; nj < 4; nj++) {
            int col = bn + wn + nj * 8 + c0 * 2;
            if (col < N) {
                float2 v0 = make_float2(acc[mi][nj][0], acc[mi][nj][1]);
                float2 v1 = make_float2(acc[mi][nj][2], acc[mi][nj][3]);
                *(float2*)&C[(size_t)row * N + col] = v0;
                *(float2*)&C[(size_t)(row + 8) * N + col] = v1;
            }
        }
    }
}

// ------- FP16 GEMM + fused LayerNorm: M64 x N256 tile, rows complete --------
// out_h[row] = LN( acc*scale(ss) + bias + res ), written as half.
__global__ void __launch_bounds__(256, 2)
gemm_ln(const __half* __restrict__ A, const __half* __restrict__ W,
        const float* __restrict__ bias, const float* __restrict__ ssbuf,
        const __half* __restrict__ res,
        const float* __restrict__ lnw, const float* __restrict__ lnb,
        __half* __restrict__ outh, int K) {
    extern __shared__ __half dsm[];
    __shared__ float part[64][4][2];
    __shared__ float2 smv[64];
    const int bm = blockIdx.x * 64;
    const int tid = threadIdx.x, lane = tid & 31, warp = tid >> 5;
    const int wmr = (warp & 1) * 32, wnc = (warp >> 1) * 64;
    const int r0 = lane >> 2, c0 = lane & 3;

    float acc[2][8][4];
#pragma unroll
    for (int i = 0; i < 2; i++)
#pragma unroll
        for (int j = 0; j < 8; j++)
#pragma unroll
            for (int k = 0; k < 4; k++) acc[i][j][k] = 0.f;

    // loader: A rows 0..63 (tid<128), B rows tid>>1 and (tid>>1)+128
    const int lrow = tid >> 1, lch = (tid & 1) * 8;
    const __half* Ap = A + (size_t)(bm + lrow) * K + lch;      // valid for tid<128
    const __half* Bp0 = W + (size_t)lrow * K + lch;
    const __half* Bp1 = W + (size_t)(lrow + 128) * K + lch;

    const uint32_t base = (uint32_t)__cvta_generic_to_shared(dsm);
    const uint32_t ASTG = 64u * SMH * 2u;          // 3072 B
    const uint32_t BSTG = 256u * SMH * 2u;         // 12288 B
    const uint32_t bbase = base + 4u * ASTG;
    const uint32_t dofA = (uint32_t)(lrow * SMH + lch) * 2u;
    const uint32_t dofB0 = dofA;
    const uint32_t dofB1 = (uint32_t)((lrow + 128) * SMH + lch) * 2u;
    const bool doA = tid < 128;

    const int lane7 = lane & 7;
    const int arow8 = ((lane >> 3) & 1) * 8, acol8 = ((lane >> 4) & 1) * 8;
    const int brow8 = ((lane >> 4) & 1) * 8, bcol8 = ((lane >> 3) & 1) * 8;
    uint32_t aAf[2], aBf[4];
#pragma unroll
    for (int mi = 0; mi < 2; mi++)
        aAf[mi] = base + (uint32_t)(((wmr + mi * 16 + lane7 + arow8) * SMH + acol8) * 2);
#pragma unroll
    for (int njp = 0; njp < 4; njp++)
        aBf[njp] = bbase + (uint32_t)(((wnc + njp * 16 + lane7 + brow8) * SMH + bcol8) * 2);

    const int KT = K >> 4;

#define LOADT(kt, buf)                                                   \
    do {                                                                 \
        int ko = (kt) * 16;                                              \
        uint32_t aA = base + (uint32_t)(buf) * ASTG;                     \
        uint32_t aB = bbase + (uint32_t)(buf) * BSTG;                    \
        if (doA) cpa16(aA + dofA, Ap + ko, 16);                          \
        cpa16(aB + dofB0, Bp0 + ko, 16);                                 \
        cpa16(aB + dofB1, Bp1 + ko, 16);                                 \
        asm volatile("cp.async.commit_group;");                          \
    } while (0)

    LOADT(0, 0);
    if (KT > 1) LOADT(1, 1);
    if (KT > 2) LOADT(2, 2);
    for (int kt = 0; kt < KT; kt++) {
        if (kt < KT - 3) asm volatile("cp.async.wait_group 2;");
        else             asm volatile("cp.async.wait_group 0;");
        __syncthreads();
        if (kt + 3 < KT) LOADT(kt + 3, (kt + 3) & 3);
        const int buf = kt & 3;
        const uint32_t aoff = (uint32_t)buf * ASTG;
        const uint32_t boff = (uint32_t)buf * BSTG;

        uint32_t af[2][4], bf[4][4];
#pragma unroll
        for (int mi = 0; mi < 2; mi++) ldm_x4(aAf[mi] + aoff, af[mi]);
#pragma unroll
        for (int njp = 0; njp < 4; njp++) ldm_x4(aBf[njp] + boff, bf[njp]);
#pragma unroll
        for (int mi = 0; mi < 2; mi++)
#pragma unroll
            for (int nj = 0; nj < 8; nj++)
                mma_f16(acc[mi][nj], af[mi], &bf[nj >> 1][(nj & 1) * 2]);
    }
#undef LOADT

    // ---- epilogue: v = acc*sc + bias + res; row mean/var; LN; store half ----
    float psum[2][2] = {{0.f,0.f},{0.f,0.f}}, psq[2][2] = {{0.f,0.f},{0.f,0.f}};
#pragma unroll
    for (int mi = 0; mi < 2; mi++) {
        const int rb0 = wmr + mi * 16 + r0;
        const int rg0 = bm + rb0, rg1 = rg0 + 8;
        float s0 = 1.f, s1 = 1.f;
        if (ssbuf != nullptr) {
            s0 = rsqrtf((ssbuf[rg0] + ssbuf[TOK + rg0]) * (1.f / DI) + 1e-5f);
            s1 = rsqrtf((ssbuf[rg1] + ssbuf[TOK + rg1]) * (1.f / DI) + 1e-5f);
        }
#pragma unroll
        for (int nj = 0; nj < 8; nj++) {
            const int col = wnc + nj * 8 + c0 * 2;
            float b0 = 0.f, b1 = 0.f;
            if (bias != nullptr) { b0 = bias[col]; b1 = bias[col + 1]; }
            float v0 = acc[mi][nj][0] * s0 + b0;
            float v1 = acc[mi][nj][1] * s0 + b1;
            float v2 = acc[mi][nj][2] * s1 + b0;
            float v3 = acc[mi][nj][3] * s1 + b1;
            if (res != nullptr) {
                __half2 r0h = *(const __half2*)(res + (size_t)rg0 * DM + col);
                __half2 r1h = *(const __half2*)(res + (size_t)rg1 * DM + col);
                v0 += __low2float(r0h); v1 += __high2float(r0h);
                v2 += __low2float(r1h); v3 += __high2float(r1h);
            }
            acc[mi][nj][0] = v0; acc[mi][nj][1] = v1;
            acc[mi][nj][2] = v2; acc[mi][nj][3] = v3;
            psum[mi][0] += v0 + v1; psq[mi][0] += v0 * v0 + v1 * v1;
            psum[mi][1] += v2 + v3; psq[mi][1] += v2 * v2 + v3 * v3;
        }
    }
#pragma unroll
    for (int mi = 0; mi < 2; mi++)
#pragma unroll
        for (int hf = 0; hf < 2; hf++) {
            float s = psum[mi][hf], q = psq[mi][hf];
            s += __shfl_xor_sync(0xffffffffu, s, 1);
            q += __shfl_xor_sync(0xffffffffu, q, 1);
            s += __shfl_xor_sync(0xffffffffu, s, 2);
            q += __shfl_xor_sync(0xffffffffu, q, 2);
            if (c0 == 0) {
                int rb = wmr + mi * 16 + r0 + hf * 8;
                part[rb][warp >> 1][0] = s;
                part[rb][warp >> 1][1] = q;
            }
        }
    __syncthreads();
    if (tid < 64) {
        float s = part[tid][0][0] + part[tid][1][0] + part[tid][2][0] + part[tid][3][0];
        float q = part[tid][0][1] + part[tid][1][1] + part[tid][2][1] + part[tid][3][1];
        float mean = s * (1.f / DM);
        float var  = q * (1.f / DM) - mean * mean;
        smv[tid] = make_float2(mean, rsqrtf(var + 1e-5f));
    }
    __syncthreads();
#pragma unroll
    for (int mi = 0; mi < 2; mi++) {
        const int rb0 = wmr + mi * 16 + r0;
        const int rg0 = bm + rb0, rg1 = rg0 + 8;
        const float2 mv0 = smv[rb0], mv1 = smv[rb0 + 8];
#pragma unroll
        for (int nj = 0; nj < 8; nj++) {
            const int col = wnc + nj * 8 + c0 * 2;
            const float w0 = lnw[col], w1 = lnw[col + 1];
            const float bb0 = lnb[col], bb1 = lnb[col + 1];
            __half2 o0 = __floats2half2_rn(
                (acc[mi][nj][0] - mv0.x) * mv0.y * w0 + bb0,
                (acc[mi][nj][1] - mv0.x) * mv0.y * w1 + bb1);
            __half2 o1 = __floats2half2_rn(
                (acc[mi][nj][2] - mv1.x) * mv1.y * w0 + bb0,
                (acc[mi][nj][3] - mv1.x) * mv1.y * w1 + bb1);
            *(__half2*)(outh + (size_t)rg0 * DM + col) = o0;
            *(__half2*)(outh + (size_t)rg1 * DM + col) = o1;
        }
    }
}

// ---------------- weight prep: half-round; fold norm_w into out_proj --------
__global__ void k_prepw(const float* __restrict__ wi, const float* __restrict__ wo,
                        const float* __restrict__ nwp) {
    int idx = blockIdx.x * blockDim.x + threadIdx.x;
    if (idx < NW_IN) {
        g_wrnd[idx] = __float2half_rn(wi[idx]);
    } else if (idx < NW_IN + NW_OUT) {
        int j = idx - NW_IN;
        int l = j / (DM * DI);
        int k = j % DI;
        g_wrnd[idx] = __float2half_rn(wo[j] * nwp[l * DI + k]);
    }
}

// ---------------- encoder ---------------------------------------------------
__global__ void k_sconv(const float* __restrict__ x, const float* __restrict__ w,
                        const float* __restrict__ bias) {
    int c = blockIdx.x, b = blockIdx.y, t = threadIdx.x;
    float v = 0.f;
    if (c < NCH) {
        const float* xr = x + (size_t)(b * NCH + c) * NT;
        float w0 = w[c * 3], w1 = w[c * 3 + 1], w2 = w[c * 3 + 2];
        float xm = (t > 0) ? xr[t - 1] : 0.f;
        float x0 = xr[t];
        float xp = (t < NT - 1) ? xr[t + 1] : 0.f;
        v = xm * w0 + x0 * w1 + xp * w2 + bias[c];
    }
    g_xsr[(size_t)(b * NT + t) * KPAD + c] = __float2half_rn(v);
}

// mixprep + biasenc fold
__global__ void k_mixprep(const float* __restrict__ mw,
                          const float* __restrict__ emb, const float* __restrict__ mb) {
    __shared__ float sb[4][64];
    int idx = blockIdx.x * blockDim.x + threadIdx.x;
    if (idx < DM * KPAD) {
        int d = idx / KPAD, k = idx % KPAD;
        g_mixw[idx] = __float2half_rn((k < NCH) ? mw[d * NCH + k] : 0.f);
    }
    if (blockIdx.x < 4) {
        int d = (blockIdx.x << 6) + (threadIdx.x & 63);
        int cg = threadIdx.x >> 6;
        float s = 0.f;
        for (int c = cg; c < NCH; c += 4) s += emb[c * DM + d];
        sb[cg][threadIdx.x & 63] = s;
        __syncthreads();
        if (threadIdx.x < 64) {
            int dd = (blockIdx.x << 6) + threadIdx.x;
            g_biasenc[dd] = mb[dd] +
                (sb[0][threadIdx.x] + sb[1][threadIdx.x] +
                 sb[2][threadIdx.x] + sb[3][threadIdx.x]) * (1.f / NCH);
        }
    }
}

// -------- B/C conv+silu and dt/dA precompute into g_bc -----------------------
__global__ void k_bc(const float* __restrict__ cw, const float* __restrict__ cb,
                     const float* __restrict__ dtb, const float* __restrict__ alog) {
    const int b = blockIdx.x;
    const int t0 = blockIdx.y * TSEG;
    const int tid = threadIdx.x;
    const float* zb = g_zx + (size_t)(b * NT) * DPROJ;
    for (int i = tid; i < TSEG * 64; i += 256) {
        const int tl = i >> 6, j = i & 63;
        const int t = t0 + tl;
        const int bt = b * NT + t;
        float outv;
        if (j < 32) {
            const int cc = 512 + j;
            float acc = cb[cc];
            const float* wr = cw + cc * 4;
#pragma unroll
            for (int q = 0; q < 4; q++) {
                int tt = t - 3 + q;
                if (tt >= 0) acc = fmaf(zb[(size_t)tt * DPROJ + DI + cc], wr[q], acc);
            }
            outv = siluf(acc);
        } else {
            const int hh = j & 15;
            float raw = zb[(size_t)t * DPROJ + DI + CONVD + hh] + dtb[hh];
            float d = raw > 20.f ? raw : log1pf(expf(raw));
            outv = (j < 48) ? expf(-d * expf(alog[hh])) : d;
        }
        g_bc[(size_t)bt * 64 + j] = outv;
    }
}

// ---------------- megascan: x-conv+silu+scan+gate+ssq ------------------------
__global__ void k_scan4(const float* __restrict__ cw, const float* __restrict__ cb,
                        const float* __restrict__ Dsk) {
    const int b = blockIdx.x, half = blockIdx.y;
    const int tid = threadIdx.x;                 // 256
    const int h = tid >> 4, p = (tid & 15) + half * 16;
    const int c = h * HD + p;
    const int warp = tid >> 5, lane = tid & 31;
    __shared__ float sB[TTILE][16], sC[TTILE][16];
    __shared__ float sA[TTILE][16], sT[TTILE][16];
    __shared__ float wss[8][NT];

    const float xw0 = cw[c * 4], xw1 = cw[c * 4 + 1];
    const float xw2 = cw[c * 4 + 2], xw3 = cw[c * 4 + 3];
    const float xb = cb[c];
    const float Dh = Dsk[h];
    const int base = b * NT;
    const float* zb = g_zx + (size_t)base * DPROJ;
    const float* bcb = g_bc + (size_t)base * 64;

    float st[DSTATE];
#pragma unroll
    for (int n = 0; n < DSTATE; n++) st[n] = 0.f;
    float hx0 = 0.f, hx1 = 0.f, hx2 = 0.f;

    for (int t0 = 0; t0 < NT; t0 += TTILE) {
        float zg[TTILE], zc[TTILE];
#pragma unroll
        for (int tl = 0; tl < TTILE; tl++) {
            zg[tl] = __ldg(zb + (size_t)(t0 + tl) * DPROJ + c);
            zc[tl] = __ldg(zb + (size_t)(t0 + tl) * DPROJ + DI + c);
        }

        __syncthreads();
#pragma unroll
        for (int i = tid; i < TTILE * 64; i += 256) {
            const int tl = i >> 6, j = i & 63;
            const float v = __ldg(bcb + (size_t)(t0 + tl) * 64 + j);
            if (j < 16)      sB[tl][j] = v;
            else if (j < 32) sC[tl][j - 16] = v;
            else if (j < 48) sA[tl][j - 32] = v;
            else             sT[tl][j - 48] = v;
        }
        __syncthreads();

#pragma unroll
        for (int tl = 0; tl < TTILE; tl++) {
            const float v3 = zc[tl];
            const float xp = siluf(xb + xw0 * hx0 + xw1 * hx1 + xw2 * hx2 + xw3 * v3);
            hx0 = hx1; hx1 = hx2; hx2 = v3;

            const float dAh = sA[tl][h];
            const float dtx = sT[tl][h] * xp;
            float a0 = 0.f, a1 = 0.f;
#pragma unroll
            for (int n = 0; n < DSTATE; n += 2) {
                st[n]     = fmaf(dAh, st[n],     dtx * sB[tl][n]);
                st[n + 1] = fmaf(dAh, st[n + 1], dtx * sB[tl][n + 1]);
                a0 = fmaf(st[n],     sC[tl][n],     a0);
                a1 = fmaf(st[n + 1], sC[tl][n + 1], a1);
            }
            const __half hv = __float2half_rn((a0 + a1 + xp * Dh) * siluf(zg[tl]));
            g_y[(size_t)(base + t0 + tl) * DI + c] = hv;

            const float ov = __half2float(hv);
            float o2 = ov * ov;
#pragma unroll
            for (int o = 16; o > 0; o >>= 1) o2 += __shfl_xor_sync(0xffffffffu, o2, o);
            if (lane == 0) wss[warp][t0 + tl] = o2;
        }
    }

    __syncthreads();
    for (int t = tid; t < NT; t += 256) {
        float s = 0.f;
#pragma unroll
        for (int w = 0; w < 8; w++) s += wss[w][t];
        g_ss[half * TOK + base + t] = s;
    }
}

// ---------------- fused pool + head ------------------------------------------
__global__ void k_poolhead(const float* __restrict__ w1, const float* __restrict__ b1,
                           const float* __restrict__ w2, const float* __restrict__ b2,
                           float* __restrict__ out) {
    __shared__ float sp[DM];
    __shared__ float sh[4];
    int b = blockIdx.x, tid = threadIdx.x;    // 256
    float s = 0.f;
    for (int t = 0; t < NT; t++) s += __half2float(g_h[(size_t)(b * NT + t) * DM + tid]);
    sp[tid] = s * (1.f / NT);
    __syncthreads();
    if (tid < 128) {
        float acc = b1[tid];
        const float* wr = w1 + tid * DM;
#pragma unroll 8
        for (int k = 0; k < DM; k++) acc = fmaf(sp[k], wr[k], acc);
        float r = fmaxf(acc, 0.f) * w2[tid];
#pragma unroll
        for (int o = 16; o > 0; o >>= 1) r += __shfl_xor_sync(0xffffffffu, r, o);
        int lane = tid & 31, wid = tid >> 5;
        if (lane == 0) sh[wid] = r;
    }
    __syncthreads();
    if (tid == 0) out[b] = sh[0] + sh[1] + sh[2] + sh[3] + b2[0];
}

// ---------------- launch -----------------------------------------------------
extern "C" void kernel_launch(void* const* d_in, const int* in_sizes, int n_in,
                              void* d_out, int out_size) {
    const float* x         = (const float*)d_in[0];
    const float* emb       = (const float*)d_in[1];
    const float* sconv_w   = (const float*)d_in[2];
    const float* sconv_b   = (const float*)d_in[3];
    const float* mixer_w   = (const float*)d_in[4];
    const float* mixer_b   = (const float*)d_in[5];
    const float* enc_ln_w  = (const float*)d_in[6];
    const float* enc_ln_b  = (const float*)d_in[7];
    const float* in_proj_w = (const float*)d_in[8];
    const float* conv_w    = (const float*)d_in[9];
    const float* conv_b    = (const float*)d_in[10];
    const float* dt_bias   = (const float*)d_in[11];
    const float* A_log     = (const float*)d_in[12];
    const float* D_skip    = (const float*)d_in[13];
    const float* norm_w    = (const float*)d_in[14];
    const float* out_proj_w= (const float*)d_in[15];
    const float* ln_w      = (const float*)d_in[16];
    const float* ln_b      = (const float*)d_in[17];
    const float* h1w       = (const float*)d_in[18];
    const float* h1b       = (const float*)d_in[19];
    const float* h2w       = (const float*)d_in[20];
    const float* h2b       = (const float*)d_in[21];
    float* out = (float*)d_out;

    __half *xsr, *mixw, *h, *y, *wrnd;
    float *biasenc, *zx, *ss;
    cudaGetSymbolAddress((void**)&xsr,     g_xsr);
    cudaGetSymbolAddress((void**)&mixw,    g_mixw);
    cudaGetSymbolAddress((void**)&biasenc, g_biasenc);
    cudaGetSymbolAddress((void**)&h,       g_h);
    cudaGetSymbolAddress((void**)&zx,      g_zx);
    cudaGetSymbolAddress((void**)&y,       g_y);
    cudaGetSymbolAddress((void**)&wrnd,    g_wrnd);
    cudaGetSymbolAddress((void**)&ss,      g_ss);

    cudaFuncSetAttribute(gemm_f16, cudaFuncAttributeMaxDynamicSharedMemorySize, GSMEM);
    cudaFuncSetAttribute(gemm_ln, cudaFuncAttributeMaxDynamicSharedMemorySize, GSMEM_LN);

    // prep
    k_prepw<<<(NW_IN + NW_OUT + 255) / 256, 256>>>(in_proj_w, out_proj_w, norm_w);
    k_sconv<<<dim3(KPAD, BB), NT>>>(x, sconv_w, sconv_b);
    k_mixprep<<<(DM * KPAD + 255) / 256, 256>>>(mixer_w, emb, mixer_b);

    // encoder: gemm + fused LN -> h (half)
    gemm_ln<<<TOK / 64, 256, GSMEM_LN>>>(xsr, mixw, biasenc, nullptr, nullptr,
                                         enc_ln_w, enc_ln_b, h, KPAD);

    // mamba2 layers
    for (int l = 0; l < NL; l++) {
        gemm_f16<<<dim3((DPROJ + 127) / 128, TOK / 128), 256, GSMEM>>>(
            h, wrnd + (size_t)l * DPROJ * DM, zx, TOK, DPROJ, DM);
        k_bc<<<dim3(BB, NT / TSEG), 256>>>(conv_w + (size_t)l * CONVD * 4,
                                           conv_b + (size_t)l * CONVD,
                                           dt_bias + l * NH, A_log + l * NH);
        k_scan4<<<dim3(BB, 2), 256>>>(conv_w + (size_t)l * CONVD * 4,
                                      conv_b + (size_t)l * CONVD,
                                      D_skip + l * NH);
        gemm_ln<<<TOK / 64, 256, GSMEM_LN>>>(
            y, wrnd + NW_IN + (size_t)l * DM * DI, nullptr, ss, h,
            ln_w + l * DM, ln_b + l * DM, h, DI);
    }

    // head
    k_poolhead<<<BB, 256>>>(h1w, h1b, h2w, h2b, out);
}

// round 15
// speedup vs baseline: 1.0685x; 1.0381x over previous
#include <cuda_runtime.h>
#include <cuda_fp16.h>
#include <stdint.h>
#include <math.h>

#define BB     64
#define NCH    129
#define NT     200
#define DM     256
#define DSTATE 16
#define HD     32
#define NL     4
#define DI     512
#define NH     16
#define CONVD  544
#define DPROJ  1072
#define TOK    (BB*NT)   // 12800
#define KPAD   144
#define SMH    24        // smem row stride in halfs -> ldmatrix conflict-free
#define TTILE  20
#define TSEG   25

#define NW_IN  (NL*DPROJ*DM)
#define NW_OUT (NL*DM*DI)
#define STAGEB (128*SMH*2)            // 6144 B per matrix per stage (gemm_f16)
#define GSMEM  (4*2*STAGEB)           // 49152 B
#define GSMEM_LN (4*(64+256)*SMH*2)   // 61440 B (gemm_ln: A 64 rows, B 256 rows)

// ---------------- scratch ---------------------------------------------------
__device__ __align__(16) __half g_xsr[TOK*KPAD];
__device__ __align__(16) __half g_mixw[DM*KPAD];
__device__ float  g_biasenc[DM];
__device__ __align__(16) __half g_h[TOK*DM];
__device__ __align__(16) __half g_zx[TOK*DPROJ];
__device__ float  g_bc[TOK*64];       // [B16, C16, dA16, dt16] per token
__device__ __align__(16) __half g_y[TOK*DI];
__device__ float  g_ss[2*TOK];
__device__ __align__(16) __half g_wrnd[NW_IN + NW_OUT];

// ---------------- helpers ---------------------------------------------------
__device__ __forceinline__ float siluf(float x) { return x / (1.f + expf(-x)); }

__device__ __forceinline__ void mma_f16(float* c, const uint32_t* a, const uint32_t* b) {
    asm volatile("mma.sync.aligned.m16n8k16.row.col.f32.f16.f16.f32 "
        "{%0,%1,%2,%3}, {%4,%5,%6,%7}, {%8,%9}, {%0,%1,%2,%3};"
        : "+f"(c[0]), "+f"(c[1]), "+f"(c[2]), "+f"(c[3])
        : "r"(a[0]), "r"(a[1]), "r"(a[2]), "r"(a[3]), "r"(b[0]), "r"(b[1]));
}
__device__ __forceinline__ void cpa16(uint32_t dst, const void* src, int sz) {
    asm volatile("cp.async.ca.shared.global [%0], [%1], 16, %2;"
                 :: "r"(dst), "l"(src), "r"(sz));
}
__device__ __forceinline__ void ldm_x4(uint32_t addr, uint32_t* r) {
    asm volatile("ldmatrix.sync.aligned.m8n8.x4.shared.b16 {%0,%1,%2,%3}, [%4];"
        : "=r"(r[0]), "=r"(r[1]), "=r"(r[2]), "=r"(r[3]) : "r"(addr));
}

// ---------------- FP16 GEMM, 4-stage K16, ldmatrix, half output -------------
__global__ void __launch_bounds__(256, 2)
gemm_f16(const __half* __restrict__ A, const __half* __restrict__ W,
         __half* __restrict__ C, int M, int N, int K) {
    extern __shared__ __half dsm[];
    const int bm = blockIdx.y * 128, bn = blockIdx.x * 128;
    const int tid = threadIdx.x, lane = tid & 31, warp = tid >> 5;
    const int wm = (warp & 1) * 64, wn = (warp >> 1) * 32;
    const int r0 = lane >> 2, c0 = lane & 3;

    float acc[4][4][4];
#pragma unroll
    for (int i = 0; i < 4; i++)
#pragma unroll
        for (int j = 0; j < 4; j++)
#pragma unroll
            for (int k = 0; k < 4; k++) acc[i][j][k] = 0.f;

    const int lrow = tid >> 1, lch = (tid & 1) * 8;
    const __half* Ap = A + (size_t)(bm + lrow) * K + lch;
    const int bnr = bn + lrow;
    const __half* Bp = W + (size_t)(bnr < N ? bnr : 0) * K + lch;
    const int szb = bnr < N ? 16 : 0;

    const uint32_t base = (uint32_t)__cvta_generic_to_shared(dsm);
    const uint32_t dof = (uint32_t)(lrow * SMH + lch) * 2u;

    const int lane7 = lane & 7;
    const int arow8 = ((lane >> 3) & 1) * 8, acol8 = ((lane >> 4) & 1) * 8;
    const int brow8 = ((lane >> 4) & 1) * 8, bcol8 = ((lane >> 3) & 1) * 8;
    uint32_t aAf[4], aBf[2];
#pragma unroll
    for (int mi = 0; mi < 4; mi++)
        aAf[mi] = base + (uint32_t)(((wm + mi * 16 + lane7 + arow8) * SMH + acol8) * 2);
#pragma unroll
    for (int njp = 0; njp < 2; njp++)
        aBf[njp] = base + 4u * STAGEB +
                   (uint32_t)(((wn + njp * 16 + lane7 + brow8) * SMH + bcol8) * 2);

    const int KT = K >> 4;

#define LOADT(kt, buf)                                                   \
    do {                                                                 \
        int ko = (kt) * 16;                                              \
        uint32_t aA = base + (uint32_t)(buf) * STAGEB;                   \
        uint32_t aB = base + (uint32_t)(4 + (buf)) * STAGEB;             \
        cpa16(aA + dof, Ap + ko, 16);                                    \
        cpa16(aB + dof, Bp + ko, szb);                                   \
        asm volatile("cp.async.commit_group;");                          \
    } while (0)

    LOADT(0, 0);
    if (KT > 1) LOADT(1, 1);
    if (KT > 2) LOADT(2, 2);
    for (int kt = 0; kt < KT; kt++) {
        if (kt < KT - 3) asm volatile("cp.async.wait_group 2;");
        else             asm volatile("cp.async.wait_group 0;");
        __syncthreads();
        if (kt + 3 < KT) LOADT(kt + 3, (kt + 3) & 3);
        const uint32_t cboff = (uint32_t)(kt & 3) * STAGEB;

        uint32_t af[4][4], bf[2][4];
#pragma unroll
        for (int mi = 0; mi < 4; mi++) ldm_x4(aAf[mi] + cboff, af[mi]);
#pragma unroll
        for (int njp = 0; njp < 2; njp++) ldm_x4(aBf[njp] + cboff, bf[njp]);
#pragma unroll
        for (int mi = 0; mi < 4; mi++)
#pragma unroll
            for (int nj = 0; nj < 4; nj++)
                mma_f16(acc[mi][nj], af[mi], &bf[nj >> 1][(nj & 1) * 2]);
    }
#undef LOADT

#pragma unroll
    for (int mi = 0; mi < 4; mi++) {
        int row = bm + wm + mi * 16 + r0;
#pragma unroll
        for (int nj = 0; nj < 4; nj++) {
            int col = bn + wn + nj * 8 + c0 * 2;
            if (col < N) {
                *(__half2*)&C[(size_t)row * N + col] =
                    __floats2half2_rn(acc[mi][nj][0], acc[mi][nj][1]);
                *(__half2*)&C[(size_t)(row + 8) * N + col] =
                    __floats2half2_rn(acc[mi][nj][2], acc[mi][nj][3]);
            }
        }
    }
}

// ------- FP16 GEMM + fused LayerNorm: M64 x N256 tile, rows complete --------
__global__ void __launch_bounds__(256, 2)
gemm_ln(const __half* __restrict__ A, const __half* __restrict__ W,
        const float* __restrict__ bias, const float* __restrict__ ssbuf,
        const __half* __restrict__ res,
        const float* __restrict__ lnw, const float* __restrict__ lnb,
        __half* __restrict__ outh, int K) {
    extern __shared__ __half dsm[];
    __shared__ float part[64][4][2];
    __shared__ float2 smv[64];
    const int bm = blockIdx.x * 64;
    const int tid = threadIdx.x, lane = tid & 31, warp = tid >> 5;
    const int wmr = (warp & 1) * 32, wnc = (warp >> 1) * 64;
    const int r0 = lane >> 2, c0 = lane & 3;

    float acc[2][8][4];
#pragma unroll
    for (int i = 0; i < 2; i++)
#pragma unroll
        for (int j = 0; j < 8; j++)
#pragma unroll
            for (int k = 0; k < 4; k++) acc[i][j][k] = 0.f;

    const int lrow = tid >> 1, lch = (tid & 1) * 8;
    const __half* Ap = A + (size_t)(bm + lrow) * K + lch;
    const __half* Bp0 = W + (size_t)lrow * K + lch;
    const __half* Bp1 = W + (size_t)(lrow + 128) * K + lch;

    const uint32_t base = (uint32_t)__cvta_generic_to_shared(dsm);
    const uint32_t ASTG = 64u * SMH * 2u;
    const uint32_t BSTG = 256u * SMH * 2u;
    const uint32_t bbase = base + 4u * ASTG;
    const uint32_t dofA = (uint32_t)(lrow * SMH + lch) * 2u;
    const uint32_t dofB1 = (uint32_t)((lrow + 128) * SMH + lch) * 2u;
    const bool doA = tid < 128;

    const int lane7 = lane & 7;
    const int arow8 = ((lane >> 3) & 1) * 8, acol8 = ((lane >> 4) & 1) * 8;
    const int brow8 = ((lane >> 4) & 1) * 8, bcol8 = ((lane >> 3) & 1) * 8;
    uint32_t aAf[2], aBf[4];
#pragma unroll
    for (int mi = 0; mi < 2; mi++)
        aAf[mi] = base + (uint32_t)(((wmr + mi * 16 + lane7 + arow8) * SMH + acol8) * 2);
#pragma unroll
    for (int njp = 0; njp < 4; njp++)
        aBf[njp] = bbase + (uint32_t)(((wnc + njp * 16 + lane7 + brow8) * SMH + bcol8) * 2);

    const int KT = K >> 4;

#define LOADT(kt, buf)                                                   \
    do {                                                                 \
        int ko = (kt) * 16;                                              \
        uint32_t aA = base + (uint32_t)(buf) * ASTG;                     \
        uint32_t aB = bbase + (uint32_t)(buf) * BSTG;                    \
        if (doA) cpa16(aA + dofA, Ap + ko, 16);                          \
        cpa16(aB + dofA, Bp0 + ko, 16);                                  \
        cpa16(aB + dofB1, Bp1 + ko, 16);                                 \
        asm volatile("cp.async.commit_group;");                          \
    } while (0)

    LOADT(0, 0);
    if (KT > 1) LOADT(1, 1);
    if (KT > 2) LOADT(2, 2);
    for (int kt = 0; kt < KT; kt++) {
        if (kt < KT - 3) asm volatile("cp.async.wait_group 2;");
        else             asm volatile("cp.async.wait_group 0;");
        __syncthreads();
        if (kt + 3 < KT) LOADT(kt + 3, (kt + 3) & 3);
        const int buf = kt & 3;
        const uint32_t aoff = (uint32_t)buf * ASTG;
        const uint32_t boff = (uint32_t)buf * BSTG;

        uint32_t af[2][4], bf[4][4];
#pragma unroll
        for (int mi = 0; mi < 2; mi++) ldm_x4(aAf[mi] + aoff, af[mi]);
#pragma unroll
        for (int njp = 0; njp < 4; njp++) ldm_x4(aBf[njp] + boff, bf[njp]);
#pragma unroll
        for (int mi = 0; mi < 2; mi++)
#pragma unroll
            for (int nj = 0; nj < 8; nj++)
                mma_f16(acc[mi][nj], af[mi], &bf[nj >> 1][(nj & 1) * 2]);
    }
#undef LOADT

    float psum[2][2] = {{0.f,0.f},{0.f,0.f}}, psq[2][2] = {{0.f,0.f},{0.f,0.f}};
#pragma unroll
    for (int mi = 0; mi < 2; mi++) {
        const int rb0 = wmr + mi * 16 + r0;
        const int rg0 = bm + rb0, rg1 = rg0 + 8;
        float s0 = 1.f, s1 = 1.f;
        if (ssbuf != nullptr) {
            s0 = rsqrtf((ssbuf[rg0] + ssbuf[TOK + rg0]) * (1.f / DI) + 1e-5f);
            s1 = rsqrtf((ssbuf[rg1] + ssbuf[TOK + rg1]) * (1.f / DI) + 1e-5f);
        }
#pragma unroll
        for (int nj = 0; nj < 8; nj++) {
            const int col = wnc + nj * 8 + c0 * 2;
            float b0 = 0.f, b1 = 0.f;
            if (bias != nullptr) { b0 = bias[col]; b1 = bias[col + 1]; }
            float v0 = acc[mi][nj][0] * s0 + b0;
            float v1 = acc[mi][nj][1] * s0 + b1;
            float v2 = acc[mi][nj][2] * s1 + b0;
            float v3 = acc[mi][nj][3] * s1 + b1;
            if (res != nullptr) {
                __half2 r0h = *(const __half2*)(res + (size_t)rg0 * DM + col);
                __half2 r1h = *(const __half2*)(res + (size_t)rg1 * DM + col);
                v0 += __low2float(r0h); v1 += __high2float(r0h);
                v2 += __low2float(r1h); v3 += __high2float(r1h);
            }
            acc[mi][nj][0] = v0; acc[mi][nj][1] = v1;
            acc[mi][nj][2] = v2; acc[mi][nj][3] = v3;
            psum[mi][0] += v0 + v1; psq[mi][0] += v0 * v0 + v1 * v1;
            psum[mi][1] += v2 + v3; psq[mi][1] += v2 * v2 + v3 * v3;
        }
    }
#pragma unroll
    for (int mi = 0; mi < 2; mi++)
#pragma unroll
        for (int hf = 0; hf < 2; hf++) {
            float s = psum[mi][hf], q = psq[mi][hf];
            s += __shfl_xor_sync(0xffffffffu, s, 1);
            q += __shfl_xor_sync(0xffffffffu, q, 1);
            s += __shfl_xor_sync(0xffffffffu, s, 2);
            q += __shfl_xor_sync(0xffffffffu, q, 2);
            if (c0 == 0) {
                int rb = wmr + mi * 16 + r0 + hf * 8;
                part[rb][warp >> 1][0] = s;
                part[rb][warp >> 1][1] = q;
            }
        }
    __syncthreads();
    if (tid < 64) {
        float s = part[tid][0][0] + part[tid][1][0] + part[tid][2][0] + part[tid][3][0];
        float q = part[tid][0][1] + part[tid][1][1] + part[tid][2][1] + part[tid][3][1];
        float mean = s * (1.f / DM);
        float var  = q * (1.f / DM) - mean * mean;
        smv[tid] = make_float2(mean, rsqrtf(var + 1e-5f));
    }
    __syncthreads();
#pragma unroll
    for (int mi = 0; mi < 2; mi++) {
        const int rb0 = wmr + mi * 16 + r0;
        const int rg0 = bm + rb0, rg1 = rg0 + 8;
        const float2 mv0 = smv[rb0], mv1 = smv[rb0 + 8];
#pragma unroll
        for (int nj = 0; nj < 8; nj++) {
            const int col = wnc + nj * 8 + c0 * 2;
            const float w0 = lnw[col], w1 = lnw[col + 1];
            const float bb0 = lnb[col], bb1 = lnb[col + 1];
            __half2 o0 = __floats2half2_rn(
                (acc[mi][nj][0] - mv0.x) * mv0.y * w0 + bb0,
                (acc[mi][nj][1] - mv0.x) * mv0.y * w1 + bb1);
            __half2 o1 = __floats2half2_rn(
                (acc[mi][nj][2] - mv1.x) * mv1.y * w0 + bb0,
                (acc[mi][nj][3] - mv1.x) * mv1.y * w1 + bb1);
            *(__half2*)(outh + (size_t)rg0 * DM + col) = o0;
            *(__half2*)(outh + (size_t)rg1 * DM + col) = o1;
        }
    }
}

// ---------------- weight prep: half-round; fold norm_w into out_proj --------
__global__ void k_prepw(const float* __restrict__ wi, const float* __restrict__ wo,
                        const float* __restrict__ nwp) {
    int idx = blockIdx.x * blockDim.x + threadIdx.x;
    if (idx < NW_IN) {
        g_wrnd[idx] = __float2half_rn(wi[idx]);
    } else if (idx < NW_IN + NW_OUT) {
        int j = idx - NW_IN;
        int l = j / (DM * DI);
        int k = j % DI;
        g_wrnd[idx] = __float2half_rn(wo[j] * nwp[l * DI + k]);
    }
}

// ---------------- encoder ---------------------------------------------------
__global__ void k_sconv(const float* __restrict__ x, const float* __restrict__ w,
                        const float* __restrict__ bias) {
    int c = blockIdx.x, b = blockIdx.y, t = threadIdx.x;
    float v = 0.f;
    if (c < NCH) {
        const float* xr = x + (size_t)(b * NCH + c) * NT;
        float w0 = w[c * 3], w1 = w[c * 3 + 1], w2 = w[c * 3 + 2];
        float xm = (t > 0) ? xr[t - 1] : 0.f;
        float x0 = xr[t];
        float xp = (t < NT - 1) ? xr[t + 1] : 0.f;
        v = xm * w0 + x0 * w1 + xp * w2 + bias[c];
    }
    g_xsr[(size_t)(b * NT + t) * KPAD + c] = __float2half_rn(v);
}

// mixprep + biasenc fold
__global__ void k_mixprep(const float* __restrict__ mw,
                          const float* __restrict__ emb, const float* __restrict__ mb) {
    __shared__ float sb[4][64];
    int idx = blockIdx.x * blockDim.x + threadIdx.x;
    if (idx < DM * KPAD) {
        int d = idx / KPAD, k = idx % KPAD;
        g_mixw[idx] = __float2half_rn((k < NCH) ? mw[d * NCH + k] : 0.f);
    }
    if (blockIdx.x < 4) {
        int d = (blockIdx.x << 6) + (threadIdx.x & 63);
        int cg = threadIdx.x >> 6;
        float s = 0.f;
        for (int c = cg; c < NCH; c += 4) s += emb[c * DM + d];
        sb[cg][threadIdx.x & 63] = s;
        __syncthreads();
        if (threadIdx.x < 64) {
            int dd = (blockIdx.x << 6) + threadIdx.x;
            g_biasenc[dd] = mb[dd] +
                (sb[0][threadIdx.x] + sb[1][threadIdx.x] +
                 sb[2][threadIdx.x] + sb[3][threadIdx.x]) * (1.f / NCH);
        }
    }
}

// -------- B/C conv+silu and dt/dA precompute into g_bc (zx is half) ---------
__global__ void k_bc(const float* __restrict__ cw, const float* __restrict__ cb,
                     const float* __restrict__ dtb, const float* __restrict__ alog) {
    const int b = blockIdx.x;
    const int t0 = blockIdx.y * TSEG;
    const int tid = threadIdx.x;
    const __half* zb = g_zx + (size_t)(b * NT) * DPROJ;
    for (int i = tid; i < TSEG * 64; i += 256) {
        const int tl = i >> 6, j = i & 63;
        const int t = t0 + tl;
        const int bt = b * NT + t;
        float outv;
        if (j < 32) {
            const int cc = 512 + j;
            float acc = cb[cc];
            const float* wr = cw + cc * 4;
#pragma unroll
            for (int q = 0; q < 4; q++) {
                int tt = t - 3 + q;
                if (tt >= 0)
                    acc = fmaf(__half2float(zb[(size_t)tt * DPROJ + DI + cc]), wr[q], acc);
            }
            outv = siluf(acc);
        } else {
            const int hh = j & 15;
            float raw = __half2float(zb[(size_t)t * DPROJ + DI + CONVD + hh]) + dtb[hh];
            float d = raw > 20.f ? raw : log1pf(expf(raw));
            outv = (j < 48) ? expf(-d * expf(alog[hh])) : d;
        }
        g_bc[(size_t)bt * 64 + j] = outv;
    }
}

// ---------------- megascan: x-conv+silu+scan+gate; deferred ssq --------------
__global__ void k_scan4(const float* __restrict__ cw, const float* __restrict__ cb,
                        const float* __restrict__ Dsk) {
    const int b = blockIdx.x, half = blockIdx.y;
    const int tid = threadIdx.x;                 // 256
    const int h = tid >> 4, p = (tid & 15) + half * 16;
    const int c = h * HD + p;
    const int warp = tid >> 5, lane = tid & 31;
    __shared__ float sB[TTILE][16], sC[TTILE][16];
    __shared__ float sA[TTILE][16], sT[TTILE][16];
    __shared__ float sYsq[TTILE][256];

    const float xw0 = cw[c * 4], xw1 = cw[c * 4 + 1];
    const float xw2 = cw[c * 4 + 2], xw3 = cw[c * 4 + 3];
    const float xb = cb[c];
    const float Dh = Dsk[h];
    const int base = b * NT;
    const __half* zb = g_zx + (size_t)base * DPROJ;
    const float* bcb = g_bc + (size_t)base * 64;

    float st[DSTATE];
#pragma unroll
    for (int n = 0; n < DSTATE; n++) st[n] = 0.f;
    float hx0 = 0.f, hx1 = 0.f, hx2 = 0.f;

    for (int t0 = 0; t0 < NT; t0 += TTILE) {
        float zg[TTILE], zc[TTILE];
#pragma unroll
        for (int tl = 0; tl < TTILE; tl++) {
            zg[tl] = __half2float(__ldg(zb + (size_t)(t0 + tl) * DPROJ + c));
            zc[tl] = __half2float(__ldg(zb + (size_t)(t0 + tl) * DPROJ + DI + c));
        }

        __syncthreads();
#pragma unroll
        for (int i = tid; i < TTILE * 64; i += 256) {
            const int tl = i >> 6, j = i & 63;
            const float v = __ldg(bcb + (size_t)(t0 + tl) * 64 + j);
            if (j < 16)      sB[tl][j] = v;
            else if (j < 32) sC[tl][j - 16] = v;
            else if (j < 48) sA[tl][j - 32] = v;
            else             sT[tl][j - 48] = v;
        }
        __syncthreads();

#pragma unroll
        for (int tl = 0; tl < TTILE; tl++) {
            const float v3 = zc[tl];
            const float xp = siluf(xb + xw0 * hx0 + xw1 * hx1 + xw2 * hx2 + xw3 * v3);
            hx0 = hx1; hx1 = hx2; hx2 = v3;

            const float dAh = sA[tl][h];
            const float dtx = sT[tl][h] * xp;
            float a0 = 0.f, a1 = 0.f;
#pragma unroll
            for (int n = 0; n < DSTATE; n += 2) {
                st[n]     = fmaf(dAh, st[n],     dtx * sB[tl][n]);
                st[n + 1] = fmaf(dAh, st[n + 1], dtx * sB[tl][n + 1]);
                a0 = fmaf(st[n],     sC[tl][n],     a0);
                a1 = fmaf(st[n + 1], sC[tl][n + 1], a1);
            }
            const __half hv = __float2half_rn((a0 + a1 + xp * Dh) * siluf(zg[tl]));
            g_y[(size_t)(base + t0 + tl) * DI + c] = hv;
            const float ov = __half2float(hv);
            sYsq[tl][tid] = ov * ov;
        }

        __syncthreads();
        // parallel per-tile ssq reduction: warp w handles tl = w, w+8, w+16
        for (int tl = warp; tl < TTILE; tl += 8) {
            float s = 0.f;
#pragma unroll
            for (int q = 0; q < 8; q++) s += sYsq[tl][lane + q * 32];
#pragma unroll
            for (int o = 16; o > 0; o >>= 1) s += __shfl_xor_sync(0xffffffffu, s, o);
            if (lane == 0) g_ss[half * TOK + base + t0 + tl] = s;
        }
    }
}

// ---------------- fused pool + head ------------------------------------------
__global__ void k_poolhead(const float* __restrict__ w1, const float* __restrict__ b1,
                           const float* __restrict__ w2, const float* __restrict__ b2,
                           float* __restrict__ out) {
    __shared__ float sp[DM];
    __shared__ float sh[4];
    int b = blockIdx.x, tid = threadIdx.x;    // 256
    float s = 0.f;
    for (int t = 0; t < NT; t++) s += __half2float(g_h[(size_t)(b * NT + t) * DM + tid]);
    sp[tid] = s * (1.f / NT);
    __syncthreads();
    if (tid < 128) {
        float acc = b1[tid];
        const float* wr = w1 + tid * DM;
#pragma unroll 8
        for (int k = 0; k < DM; k++) acc = fmaf(sp[k], wr[k], acc);
        float r = fmaxf(acc, 0.f) * w2[tid];
#pragma unroll
        for (int o = 16; o > 0; o >>= 1) r += __shfl_xor_sync(0xffffffffu, r, o);
        int lane = tid & 31, wid = tid >> 5;
        if (lane == 0) sh[wid] = r;
    }
    __syncthreads();
    if (tid == 0) out[b] = sh[0] + sh[1] + sh[2] + sh[3] + b2[0];
}

// ---------------- launch -----------------------------------------------------
extern "C" void kernel_launch(void* const* d_in, const int* in_sizes, int n_in,
                              void* d_out, int out_size) {
    const float* x         = (const float*)d_in[0];
    const float* emb       = (const float*)d_in[1];
    const float* sconv_w   = (const float*)d_in[2];
    const float* sconv_b   = (const float*)d_in[3];
    const float* mixer_w   = (const float*)d_in[4];
    const float* mixer_b   = (const float*)d_in[5];
    const float* enc_ln_w  = (const float*)d_in[6];
    const float* enc_ln_b  = (const float*)d_in[7];
    const float* in_proj_w = (const float*)d_in[8];
    const float* conv_w    = (const float*)d_in[9];
    const float* conv_b    = (const float*)d_in[10];
    const float* dt_bias   = (const float*)d_in[11];
    const float* A_log     = (const float*)d_in[12];
    const float* D_skip    = (const float*)d_in[13];
    const float* norm_w    = (const float*)d_in[14];
    const float* out_proj_w= (const float*)d_in[15];
    const float* ln_w      = (const float*)d_in[16];
    const float* ln_b      = (const float*)d_in[17];
    const float* h1w       = (const float*)d_in[18];
    const float* h1b       = (const float*)d_in[19];
    const float* h2w       = (const float*)d_in[20];
    const float* h2b       = (const float*)d_in[21];
    float* out = (float*)d_out;

    __half *xsr, *mixw, *h, *zx, *y, *wrnd;
    float *biasenc, *ss;
    cudaGetSymbolAddress((void**)&xsr,     g_xsr);
    cudaGetSymbolAddress((void**)&mixw,    g_mixw);
    cudaGetSymbolAddress((void**)&biasenc, g_biasenc);
    cudaGetSymbolAddress((void**)&h,       g_h);
    cudaGetSymbolAddress((void**)&zx,      g_zx);
    cudaGetSymbolAddress((void**)&y,       g_y);
    cudaGetSymbolAddress((void**)&wrnd,    g_wrnd);
    cudaGetSymbolAddress((void**)&ss,      g_ss);

    cudaFuncSetAttribute(gemm_f16, cudaFuncAttributeMaxDynamicSharedMemorySize, GSMEM);
    cudaFuncSetAttribute(gemm_ln, cudaFuncAttributeMaxDynamicSharedMemorySize, GSMEM_LN);

    // prep
    k_prepw<<<(NW_IN + NW_OUT + 255) / 256, 256>>>(in_proj_w, out_proj_w, norm_w);
    k_sconv<<<dim3(KPAD, BB), NT>>>(x, sconv_w, sconv_b);
    k_mixprep<<<(DM * KPAD + 255) / 256, 256>>>(mixer_w, emb, mixer_b);

    // encoder: gemm + fused LN -> h (half)
    gemm_ln<<<TOK / 64, 256, GSMEM_LN>>>(xsr, mixw, biasenc, nullptr, nullptr,
                                         enc_ln_w, enc_ln_b, h, KPAD);

    // mamba2 layers
    for (int l = 0; l < NL; l++) {
        gemm_f16<<<dim3((DPROJ + 127) / 128, TOK / 128), 256, GSMEM>>>(
            h, wrnd + (size_t)l * DPROJ * DM, zx, TOK, DPROJ, DM);
        k_bc<<<dim3(BB, NT / TSEG), 256>>>(conv_w + (size_t)l * CONVD * 4,
                                           conv_b + (size_t)l * CONVD,
                                           dt_bias + l * NH, A_log + l * NH);
        k_scan4<<<dim3(BB, 2), 256>>>(conv_w + (size_t)l * CONVD * 4,
                                      conv_b + (size_t)l * CONVD,
                                      D_skip + l * NH);
        gemm_ln<<<TOK / 64, 256, GSMEM_LN>>>(
            y, wrnd + NW_IN + (size_t)l * DM * DI, nullptr, ss, h,
            ln_w + l * DM, ln_b + l * DM, h, DI);
    }

    // head
    k_poolhead<<<BB, 256>>>(h1w, h1b, h2w, h2b, out);
}